// round 2
// baseline (speedup 1.0000x reference)
#include <cuda_runtime.h>
#include <cuda_fp16.h>
#include <mma.h>

using namespace nvcuda;

// Problem constants (fixed by the reference setup)
static constexpr int M = 4096;      // tokens
static constexpr int K = 4096;      // in_features
static constexpr int N = 11008;     // out_features
static constexpr int PACK = 8;      // nibbles per int32
static constexpr int KP = K / PACK; // 512 packed rows of qweight

// 90 MB fp16 dequantized weight scratch (static __device__ — no allocation)
__device__ __half g_W[(size_t)K * N];

// ---------------------------------------------------------------------------
// Dequant: qweight [K/8, N] int32 -> g_W [K, N] fp16
// scales arrive as float32 (exactly fp16-representable values). The product
// s * (w - zero) is exact in f32, so rounding to half reproduces the
// reference's fp16 dequant bit-for-bit.
// ---------------------------------------------------------------------------
__global__ void dequant_kernel(const int* __restrict__ qweight,
                               const int* __restrict__ qzeros,
                               const float* __restrict__ scales,
                               const int* __restrict__ g_idx) {
    int n  = blockIdx.x * blockDim.x + threadIdx.x;
    int kk = blockIdx.y;                     // 0..KP-1
    if (n >= N) return;

    int   g    = g_idx[kk * PACK];           // group for these 8 k's
    int   qw   = qweight[(size_t)kk * N + n];
    int   qz   = qzeros[(size_t)g * (N / 8) + (n >> 3)];
    int   zero = ((qz >> ((n & 7) * 4)) & 15) + 1;
    float s    = scales[(size_t)g * N + n];

    size_t base = (size_t)(kk * PACK) * N + n;
#pragma unroll
    for (int i = 0; i < 8; i++) {
        int w = ((qw >> (4 * i)) & 15) - zero;
        g_W[base + (size_t)i * N] = __float2half(s * (float)w);
    }
}

// ---------------------------------------------------------------------------
// GEMM: C[M,N] = X[M,K] @ g_W[K,N] + bias. X arrives f32 (fp16-representable),
// converted to half while staging into smem. fp32 accumulate, f32 output.
// Block tile 128x128, BK=32. 8 warps 2(M) x 4(N); warp tile 64x32.
// ---------------------------------------------------------------------------
static constexpr int BM = 128;
static constexpr int BN = 128;
static constexpr int BK = 32;
static constexpr int SKEW = 8;   // halves; 16B skew to dodge bank conflicts

__global__ __launch_bounds__(256, 1)
void gemm_kernel(const float* __restrict__ X,
                 const float* __restrict__ bias,
                 float* __restrict__ C) {
    __shared__ __half Xs[BM][BK + SKEW];
    __shared__ __half Ws[BK][BN + SKEW];
    __shared__ float  stage[8][16 * 16];   // per-warp accumulator staging

    const int tid  = threadIdx.x;
    const int warp = tid >> 5;
    const int lane = tid & 31;
    const int wm   = warp >> 2;   // 0..1 : warp row  (64 rows each)
    const int wn   = warp & 3;    // 0..3 : warp col  (32 cols each)

    const int bm = blockIdx.y * BM;
    const int bn = blockIdx.x * BN;

    wmma::fragment<wmma::accumulator, 16, 16, 16, float> acc[4][2];
#pragma unroll
    for (int i = 0; i < 4; i++)
#pragma unroll
        for (int j = 0; j < 2; j++)
            wmma::fill_fragment(acc[i][j], 0.0f);

    for (int k0 = 0; k0 < K; k0 += BK) {
        // Load X tile: 128 x 32 f32 -> half. 1024 float4, 4 per thread.
#pragma unroll
        for (int l = 0; l < 4; l++) {
            int lin = tid + l * 256;
            int r = lin >> 3;            // 8 float4 per row of 32
            int c = (lin & 7) * 4;
            float4 v = *(const float4*)&X[(size_t)(bm + r) * K + k0 + c];
            __half2* dst = (__half2*)&Xs[r][c];
            dst[0] = __floats2half2_rn(v.x, v.y);
            dst[1] = __floats2half2_rn(v.z, v.w);
        }
        // Load W tile: 32 x 128 halves = 512 float4, 2 per thread
#pragma unroll
        for (int l = 0; l < 2; l++) {
            int lin = tid + l * 256;
            int r = lin >> 4;
            int c = (lin & 15) * 8;
            *(float4*)&Ws[r][c] =
                *(const float4*)&g_W[(size_t)(k0 + r) * N + bn + c];
        }
        __syncthreads();

#pragma unroll
        for (int kk = 0; kk < BK; kk += 16) {
            wmma::fragment<wmma::matrix_a, 16, 16, 16, __half, wmma::row_major> a[4];
            wmma::fragment<wmma::matrix_b, 16, 16, 16, __half, wmma::row_major> b[2];
#pragma unroll
            for (int i = 0; i < 4; i++)
                wmma::load_matrix_sync(a[i], &Xs[wm * 64 + i * 16][kk], BK + SKEW);
#pragma unroll
            for (int j = 0; j < 2; j++)
                wmma::load_matrix_sync(b[j], &Ws[kk][wn * 32 + j * 16], BN + SKEW);
#pragma unroll
            for (int i = 0; i < 4; i++)
#pragma unroll
                for (int j = 0; j < 2; j++)
                    wmma::mma_sync(acc[i][j], a[i], b[j], acc[i][j]);
        }
        __syncthreads();
    }

    // Epilogue: stage each 16x16 acc to smem, add bias, store f32
    float* st = stage[warp];
    const int row     = lane >> 1;
    const int colbase = (lane & 1) * 8;
#pragma unroll
    for (int i = 0; i < 4; i++) {
#pragma unroll
        for (int j = 0; j < 2; j++) {
            wmma::store_matrix_sync(st, acc[i][j], 16, wmma::mem_row_major);
            __syncwarp();
            int gm = bm + wm * 64 + i * 16 + row;
            int gn = bn + wn * 32 + j * 16 + colbase;
            float* cptr = &C[(size_t)gm * N + gn];
            const float* sp = &st[row * 16 + colbase];
#pragma unroll
            for (int t = 0; t < 8; t++)
                cptr[t] = sp[t] + bias[gn + t];
            __syncwarp();
        }
    }
}

extern "C" void kernel_launch(void* const* d_in, const int* in_sizes, int n_in,
                              void* d_out, int out_size) {
    const float* x       = (const float*)d_in[0];
    const int*   qweight = (const int*)d_in[1];
    const int*   qzeros  = (const int*)d_in[2];
    const float* scales  = (const float*)d_in[3];
    const int*   g_idx   = (const int*)d_in[4];
    const float* bias    = (const float*)d_in[5];
    float*       out     = (float*)d_out;

    dim3 dq_grid((N + 255) / 256, KP);
    dequant_kernel<<<dq_grid, 256>>>(qweight, qzeros, scales, g_idx);

    dim3 gemm_grid(N / BN, M / BM);   // 86 x 32
    gemm_kernel<<<gemm_grid, 256>>>(x, bias, out);
}

// round 4
// speedup vs baseline: 2.3090x; 2.3090x over previous
#include <cuda_runtime.h>
#include <cuda_fp16.h>
#include <mma.h>
#include <cstdint>

using namespace nvcuda;

// ---------------------------------------------------------------------------
// Problem constants
// ---------------------------------------------------------------------------
static constexpr int M = 4096;      // tokens
static constexpr int K = 4096;      // in_features
static constexpr int N = 11008;     // out_features
static constexpr int KP = K / 8;    // packed qweight rows

// GEMM tiling
static constexpr int BM = 128;
static constexpr int BN = 128;
static constexpr int BK = 32;
static constexpr int STAGES = 4;
static constexpr int NIT = K / BK;          // 128
static constexpr int PAD = 8;               // halves; stride 40 -> conflict-free ldmatrix
static constexpr int LDS_T = BK + PAD;      // 40 halves = 80B row stride
static constexpr int TILE_HALFS = BM * LDS_T;         // 5120 halves = 10240B
static constexpr int STAGE_HALFS = 2 * TILE_HALFS;    // A + B
static constexpr int SMEM_BYTES = STAGES * STAGE_HALFS * 2;  // 81920

// fp16 scratch (static __device__ -- no allocation)
__device__ __half g_Wt[(size_t)N * K];   // W transposed: [N, K]
__device__ __half g_Xh[(size_t)M * K];   // x as fp16:    [M, K]

// ---------------------------------------------------------------------------
__device__ __forceinline__ uint32_t smem_u32(const void* p) {
    uint32_t a;
    asm("{ .reg .u64 t; cvta.to.shared.u64 t, %1; cvt.u32.u64 %0, t; }" : "=r"(a) : "l"(p));
    return a;
}
__device__ __forceinline__ void cp_async16(uint32_t dst, const void* src) {
    asm volatile("cp.async.cg.shared.global [%0], [%1], 16;" :: "r"(dst), "l"(src) : "memory");
}
__device__ __forceinline__ void cp_commit() {
    asm volatile("cp.async.commit_group;" ::: "memory");
}
__device__ __forceinline__ void cp_wait2() {
    asm volatile("cp.async.wait_group 2;" ::: "memory");
}
__device__ __forceinline__ void cp_wait0() {
    asm volatile("cp.async.wait_group 0;" ::: "memory");
}

// ---------------------------------------------------------------------------
// Pre-pass 1: x f32 -> g_Xh fp16
// ---------------------------------------------------------------------------
__global__ void convert_x_kernel(const float* __restrict__ x) {
    size_t base = ((size_t)blockIdx.x * blockDim.x + threadIdx.x) * 8;
    if (base >= (size_t)M * K) return;
    float4 a = *(const float4*)&x[base];
    float4 b = *(const float4*)&x[base + 4];
    __half2 h[4];
    h[0] = __floats2half2_rn(a.x, a.y);
    h[1] = __floats2half2_rn(a.z, a.w);
    h[2] = __floats2half2_rn(b.x, b.y);
    h[3] = __floats2half2_rn(b.z, b.w);
    *(uint4*)&g_Xh[base] = *(uint4*)h;
}

// ---------------------------------------------------------------------------
// Pre-pass 2: dequant to transposed g_Wt [N, K] fp16 (K-major rows).
// Thread (n, kk): 1 qweight word = 8 consecutive k -> one 16B store.
// ---------------------------------------------------------------------------
__global__ void dequant_kernel(const int* __restrict__ qweight,
                               const int* __restrict__ qzeros,
                               const float* __restrict__ scales,
                               const int* __restrict__ g_idx) {
    int n  = blockIdx.x * 32 + (threadIdx.x >> 3);
    int kk = blockIdx.y * 8  + (threadIdx.x & 7);
    if (n >= N) return;

    int   g    = g_idx[kk * 8];
    int   qw   = qweight[(size_t)kk * N + n];
    int   qz   = qzeros[(size_t)g * (N / 8) + (n >> 3)];
    int   zero = ((qz >> ((n & 7) * 4)) & 15) + 1;
    float s    = scales[(size_t)g * N + n];

    __half h[8];
#pragma unroll
    for (int i = 0; i < 8; i++) {
        int w = ((qw >> (4 * i)) & 15) - zero;
        h[i] = __float2half(s * (float)w);
    }
    *(uint4*)&g_Wt[(size_t)n * K + kk * 8] = *(uint4*)h;
}

// ---------------------------------------------------------------------------
// GEMM: C[M,N] = g_Xh[M,K] @ g_Wt[N,K]^T + bias.
// 128x128 CTA tile, BK=32, 4-stage cp.async pipeline, 8 warps 2(M)x4(N),
// warp tile 64x32 (4x2 wmma frags). B consumed as wmma col_major from [N,K].
// ---------------------------------------------------------------------------
__global__ __launch_bounds__(256, 2)
void gemm_kernel(const float* __restrict__ bias, float* __restrict__ C) {
    extern __shared__ __half smem[];
    const uint32_t sbase = smem_u32(smem);

    const int tid  = threadIdx.x;
    const int warp = tid >> 5;
    const int lane = tid & 31;
    const int wm   = warp >> 2;   // 0..1 : warp row  (64 rows each)
    const int wn   = warp & 3;    // 0..3 : warp col  (32 cols each)

    const int bm = blockIdx.y * BM;
    const int bn = blockIdx.x * BN;

    // cp.async source/dest for this thread: 2 chunks of A + 2 of B per stage.
    // chunk id = tid + l*256; row = id>>2 (4 x 16B chunks per 32-half row), c = id&3.
    const int r0 = tid >> 2;            // 0..63
    const int c0 = tid & 3;             // 0..3
    const __half* gA0 = g_Xh + (size_t)(bm + r0) * K + c0 * 8;
    const __half* gA1 = g_Xh + (size_t)(bm + r0 + 64) * K + c0 * 8;
    const __half* gB0 = g_Wt + (size_t)(bn + r0) * K + c0 * 8;
    const __half* gB1 = g_Wt + (size_t)(bn + r0 + 64) * K + c0 * 8;
    const uint32_t dA0 = (uint32_t)(r0 * LDS_T + c0 * 8) * 2;
    const uint32_t dA1 = (uint32_t)((r0 + 64) * LDS_T + c0 * 8) * 2;
    const uint32_t dB0 = dA0 + TILE_HALFS * 2;
    const uint32_t dB1 = dA1 + TILE_HALFS * 2;

    wmma::fragment<wmma::accumulator, 16, 16, 16, float> acc[4][2];
#pragma unroll
    for (int i = 0; i < 4; i++)
#pragma unroll
        for (int j = 0; j < 2; j++)
            wmma::fill_fragment(acc[i][j], 0.0f);

    // prologue: stage 0..2
#pragma unroll
    for (int s = 0; s < STAGES - 1; s++) {
        const uint32_t st = sbase + (uint32_t)(s * STAGE_HALFS) * 2;
        const size_t ko = (size_t)s * BK;
        cp_async16(st + dA0, gA0 + ko);
        cp_async16(st + dA1, gA1 + ko);
        cp_async16(st + dB0, gB0 + ko);
        cp_async16(st + dB1, gB1 + ko);
        cp_commit();
    }

    for (int i = 0; i < NIT; i++) {
        cp_wait2();
        __syncthreads();

        const int s = i & (STAGES - 1);
        const __half* As = smem + s * STAGE_HALFS;
        const __half* Bs = As + TILE_HALFS;

#pragma unroll
        for (int kk = 0; kk < BK; kk += 16) {
            wmma::fragment<wmma::matrix_a, 16, 16, 16, __half, wmma::row_major> a[4];
            wmma::fragment<wmma::matrix_b, 16, 16, 16, __half, wmma::col_major> b[2];
#pragma unroll
            for (int ii = 0; ii < 4; ii++)
                wmma::load_matrix_sync(a[ii], As + (wm * 64 + ii * 16) * LDS_T + kk, LDS_T);
#pragma unroll
            for (int j = 0; j < 2; j++)
                wmma::load_matrix_sync(b[j], Bs + (wn * 32 + j * 16) * LDS_T + kk, LDS_T);
#pragma unroll
            for (int ii = 0; ii < 4; ii++)
#pragma unroll
                for (int j = 0; j < 2; j++)
                    wmma::mma_sync(acc[ii][j], a[ii], b[j], acc[ii][j]);
        }
        __syncthreads();

        const int p = i + STAGES - 1;
        if (p < NIT) {
            const uint32_t st = sbase + (uint32_t)((p & (STAGES - 1)) * STAGE_HALFS) * 2;
            const size_t ko = (size_t)p * BK;
            cp_async16(st + dA0, gA0 + ko);
            cp_async16(st + dA1, gA1 + ko);
            cp_async16(st + dB0, gB0 + ko);
            cp_async16(st + dB1, gB1 + ko);
        }
        cp_commit();
    }
    cp_wait0();
    __syncthreads();

    // Epilogue: stage each 16x16 acc through smem, add bias, store f32.
    float* st = (float*)smem + warp * 256;
    const int row     = lane >> 1;
    const int colbase = (lane & 1) * 8;
#pragma unroll
    for (int i = 0; i < 4; i++) {
#pragma unroll
        for (int j = 0; j < 2; j++) {
            wmma::store_matrix_sync(st, acc[i][j], 16, wmma::mem_row_major);
            __syncwarp();
            int gm = bm + wm * 64 + i * 16 + row;
            int gn = bn + wn * 32 + j * 16 + colbase;
            float* cptr = &C[(size_t)gm * N + gn];
            const float* sp = &st[row * 16 + colbase];
            float4 v0, v1;
            v0.x = sp[0] + bias[gn + 0];
            v0.y = sp[1] + bias[gn + 1];
            v0.z = sp[2] + bias[gn + 2];
            v0.w = sp[3] + bias[gn + 3];
            v1.x = sp[4] + bias[gn + 4];
            v1.y = sp[5] + bias[gn + 5];
            v1.z = sp[6] + bias[gn + 6];
            v1.w = sp[7] + bias[gn + 7];
            *(float4*)cptr = v0;
            *(float4*)(cptr + 4) = v1;
            __syncwarp();
        }
    }
}

// ---------------------------------------------------------------------------
extern "C" void kernel_launch(void* const* d_in, const int* in_sizes, int n_in,
                              void* d_out, int out_size) {
    const float* x       = (const float*)d_in[0];
    const int*   qweight = (const int*)d_in[1];
    const int*   qzeros  = (const int*)d_in[2];
    const float* scales  = (const float*)d_in[3];
    const int*   g_idx   = (const int*)d_in[4];
    const float* bias    = (const float*)d_in[5];
    float*       out     = (float*)d_out;

    cudaFuncSetAttribute(gemm_kernel,
                         cudaFuncAttributeMaxDynamicSharedMemorySize, SMEM_BYTES);

    convert_x_kernel<<<((size_t)M * K / 8 + 255) / 256, 256>>>(x);

    dim3 dq_grid(N / 32, KP / 8);
    dequant_kernel<<<dq_grid, 256>>>(qweight, qzeros, scales, g_idx);

    dim3 gemm_grid(N / BN, M / BM);   // 86 x 32
    gemm_kernel<<<gemm_grid, 256, SMEM_BYTES>>>(bias, out);
}